// round 1
// baseline (speedup 1.0000x reference)
#include <cuda_runtime.h>

// ---------------------------------------------------------------------------
// FeatureQuantizerEMA — VQ-VAE EMA quantizer
// x:        [32, 256, 64, 64] f32   (in_sizes[0] = 33554432)
// embed:    [256, 1024] f32         (in_sizes[1] = 262144)
// cluster:  [1024] f32              (in_sizes[2] = 1024)
// ema:      [256, 1024] f32         (in_sizes[3] = 262144)
// outputs concatenated f32: out(33554432), loss(1), embed_idx(131072),
//   new_embed(262144), new_cluster_size(1024), new_ema_embed(262144)
// ---------------------------------------------------------------------------

#define NROWS   131072          // 32*64*64
#define KEMB    1024
#define DEMB    256
#define HWSZ    4096            // 64*64

#define OUT_OFF  0
#define LOSS_OFF 33554432
#define IDX_OFF  33554433
#define EMB_OFF  33685505
#define CS_OFF   33947649
#define EMA_OFF  33948673
#define FULL_OUT 34210817

// scratch (static device allocations are allowed)
__device__ int    g_idx[NROWS];
__device__ float  g_count[KEMB];
__device__ float  g_dw[DEMB * KEMB];
__device__ float  g_e2h[KEMB];
__device__ float  g_smooth[KEMB];
__device__ double g_lossPart[256];
__device__ float  g_spill[262144];   // fallback sink if out layout differs

union F2U { float2 f; unsigned long long u; };

__device__ __forceinline__ void ffma2(unsigned long long& d,
                                      unsigned long long a,
                                      unsigned long long b) {
    asm("fma.rn.f32x2 %0, %1, %2, %0;" : "+l"(d) : "l"(a), "l"(b));
}

// ---------------------------------------------------------------------------
// prep: zero dw/count/loss partials, compute half column norms of embed
// grid 1024 x 256
// ---------------------------------------------------------------------------
__global__ void prep_kernel(const float* __restrict__ embed) {
    int i = blockIdx.x * blockDim.x + threadIdx.x;
    if (i < DEMB * KEMB) g_dw[i] = 0.0f;
    if (i < KEMB) {
        g_count[i] = 0.0f;
        float s = 0.0f;
        #pragma unroll 4
        for (int d = 0; d < DEMB; d++) {
            float e = embed[d * KEMB + i];
            s = fmaf(e, e, s);
        }
        g_e2h[i] = 0.5f * s;
    }
    if (i < 256) g_lossPart[i] = 0.0;
}

// ---------------------------------------------------------------------------
// argmin kernel: fused fp32 GEMM (dot(x_n, e_k)) + argmin_k(e2h[k] - dot)
// CTA tile: 64 rows x 1024 codes, 256 threads (8 n-groups x 32 k-lanes)
// inner: f32x2 packed FMA, k-pairs along accumulator
// ---------------------------------------------------------------------------
__global__ __launch_bounds__(256, 2)
void argmin_kernel(const float* __restrict__ x,
                   const float* __restrict__ embed,
                   float* __restrict__ outIdxF) {
    __shared__ float2 xs2[32][64];     // 16 KB, x duplicated as (v,v)
    __shared__ float  es[32 * 256];    // 32 KB, embed chunk

    const int tid = threadIdx.x;
    const int tk = tid & 31;           // k lane
    const int tn = tid >> 5;           // n group (== warp id)
    const int n0 = blockIdx.x * 64;
    const int b  = n0 >> 12;
    const int hw0 = n0 & (HWSZ - 1);
    const float* xb = x + (size_t)b * DEMB * HWSZ + hw0;

    float bestS[8];
    int   bestK[8];
    #pragma unroll
    for (int i = 0; i < 8; i++) { bestS[i] = 3.4e38f; bestK[i] = 0; }

    for (int c = 0; c < 4; c++) {
        const int k0 = c * 256;
        unsigned long long acc[8][4];
        #pragma unroll
        for (int i = 0; i < 8; i++)
            #pragma unroll
            for (int j = 0; j < 4; j++) acc[i][j] = 0ull;

        for (int dc = 0; dc < 8; dc++) {
            const int d0 = dc * 32;
            __syncthreads();
            // fill x tile (coalesced 256B rows), duplicated pairs
            for (int i = tid; i < 2048; i += 256) {
                int dd = i >> 6, nn = i & 63;
                float v = xb[(size_t)(d0 + dd) * HWSZ + nn];
                xs2[dd][nn] = make_float2(v, v);
            }
            // fill embed tile (coalesced 1KB rows)
            for (int i = tid; i < 8192; i += 256) {
                int dd = i >> 8, kk = i & 255;
                es[dd * 256 + kk] = embed[(d0 + dd) * KEMB + k0 + kk];
            }
            __syncthreads();

            #pragma unroll 4
            for (int dd = 0; dd < 32; dd++) {
                // 8 x packs, broadcast LDS.128
                const longlong2* xr = (const longlong2*)&xs2[dd][8 * tn];
                longlong2 xp01 = xr[0], xp23 = xr[1], xp45 = xr[2], xp67 = xr[3];
                unsigned long long xp[8] = {
                    (unsigned long long)xp01.x, (unsigned long long)xp01.y,
                    (unsigned long long)xp23.x, (unsigned long long)xp23.y,
                    (unsigned long long)xp45.x, (unsigned long long)xp45.y,
                    (unsigned long long)xp67.x, (unsigned long long)xp67.y };
                // embed pairs: lane tk covers k = {4tk..4tk+3} U {128+4tk..+3}
                // -> each LDS.128 is 512B contiguous across the warp (no conflicts)
                const longlong2* er0 = (const longlong2*)&es[dd * 256 + 4 * tk];
                const longlong2* er1 = (const longlong2*)&es[dd * 256 + 128 + 4 * tk];
                longlong2 e03 = er0[0];
                longlong2 e47 = er1[0];
                unsigned long long ep[4] = {
                    (unsigned long long)e03.x, (unsigned long long)e03.y,
                    (unsigned long long)e47.x, (unsigned long long)e47.y };
                #pragma unroll
                for (int i = 0; i < 8; i++) {
                    ffma2(acc[i][0], xp[i], ep[0]);
                    ffma2(acc[i][1], xp[i], ep[1]);
                    ffma2(acc[i][2], xp[i], ep[2]);
                    ffma2(acc[i][3], xp[i], ep[3]);
                }
            }
        }

        // chunk finalize: score = e2h[k] - dot, scan in increasing k
        #pragma unroll
        for (int i = 0; i < 8; i++) {
            #pragma unroll
            for (int j2 = 0; j2 < 4; j2++) {
                F2U u; u.u = acc[i][j2];
                int kl = (j2 < 2) ? (4 * tk + 2 * j2)
                                  : (128 + 4 * tk + 2 * (j2 - 2));
                int k = k0 + kl;
                float s0 = __ldg(&g_e2h[k])     - u.f.x;
                float s1 = __ldg(&g_e2h[k + 1]) - u.f.y;
                if (s0 < bestS[i]) { bestS[i] = s0; bestK[i] = k; }
                if (s1 < bestS[i]) { bestS[i] = s1; bestK[i] = k + 1; }
            }
        }
    }

    // warp butterfly reduce per n (32 k-lanes share each of the warp's 8 rows)
    #pragma unroll
    for (int i = 0; i < 8; i++) {
        float s = bestS[i]; int k = bestK[i];
        #pragma unroll
        for (int off = 16; off; off >>= 1) {
            float so = __shfl_xor_sync(0xffffffffu, s, off);
            int   ko = __shfl_xor_sync(0xffffffffu, k, off);
            if (so < s || (so == s && ko < k)) { s = so; k = ko; }
        }
        if (tk == i) {           // lanes 0..7 each emit one row
            int n = n0 + 8 * tn + i;
            g_idx[n] = k;
            outIdxF[n] = (float)k;
            atomicAdd(&g_count[k], 1.0f);
        }
    }
}

// ---------------------------------------------------------------------------
// writeback: out = gather(embed, idx), loss partials, dw scatter
// grid 32768 x 256, 4 elements (one float4) per thread
// ---------------------------------------------------------------------------
__global__ __launch_bounds__(256)
void writeback_kernel(const float* __restrict__ x,
                      const float* __restrict__ embed,
                      float* __restrict__ out) {
    const int t = blockIdx.x * blockDim.x + threadIdx.x;
    const size_t e = (size_t)t * 4;
    const int b  = (int)(e >> 20);            // 256*4096 = 2^20
    const int rem = (int)(e & 1048575);
    const int d  = rem >> 12;
    const int hw = rem & 4095;
    const int n  = (b << 12) | hw;

    float4 xv = *(const float4*)(x + e);
    int4   kv = *(const int4*)(g_idx + n);
    const float* erow = embed + (size_t)d * KEMB;
    float q0 = __ldg(erow + kv.x);
    float q1 = __ldg(erow + kv.y);
    float q2 = __ldg(erow + kv.z);
    float q3 = __ldg(erow + kv.w);
    *(float4*)(out + e) = make_float4(q0, q1, q2, q3);

    float d0 = q0 - xv.x, d1 = q1 - xv.y, d2 = q2 - xv.z, d3 = q3 - xv.w;
    float ls = d0 * d0 + d1 * d1 + d2 * d2 + d3 * d3;

    float* dwrow = g_dw + (size_t)d * KEMB;
    atomicAdd(dwrow + kv.x, xv.x);
    atomicAdd(dwrow + kv.y, xv.y);
    atomicAdd(dwrow + kv.z, xv.z);
    atomicAdd(dwrow + kv.w, xv.w);

    // block reduce loss
    #pragma unroll
    for (int off = 16; off; off >>= 1)
        ls += __shfl_xor_sync(0xffffffffu, ls, off);
    __shared__ float wsum[8];
    int lane = threadIdx.x & 31, wid = threadIdx.x >> 5;
    if (lane == 0) wsum[wid] = ls;
    __syncthreads();
    if (threadIdx.x == 0) {
        float bs = 0.0f;
        #pragma unroll
        for (int w = 0; w < 8; w++) bs += wsum[w];
        atomicAdd(&g_lossPart[blockIdx.x & 255], (double)bs);
    }
}

// ---------------------------------------------------------------------------
// cluster-size / smoothing / loss finalize. 1 block x 1024
// ---------------------------------------------------------------------------
__global__ __launch_bounds__(1024)
void cs_kernel(const float* __restrict__ cs_in,
               float* __restrict__ outCS,
               float* __restrict__ outLoss) {
    __shared__ float red[1024];
    int k = threadIdx.x;
    float ncs = cs_in[k] * 0.9f + 0.1f * g_count[k];
    outCS[k] = ncs;
    red[k] = ncs;
    __syncthreads();
    for (int s = 512; s; s >>= 1) {
        if (k < s) red[k] += red[k + s];
        __syncthreads();
    }
    float nsum = red[0];
    g_smooth[k] = nsum * ((ncs + 1e-5f) / (nsum + ncs * 1e-5f));
    if (k == 0) {
        double ls = 0.0;
        for (int i = 0; i < 256; i++) ls += g_lossPart[i];
        outLoss[0] = (float)(0.25 * ls / 33554432.0);
    }
}

// ---------------------------------------------------------------------------
// EMA + normalized embed. grid 1024 x 256
// ---------------------------------------------------------------------------
__global__ __launch_bounds__(256)
void emb_kernel(const float* __restrict__ ema_in,
                float* __restrict__ outEmb,
                float* __restrict__ outEma) {
    int i = blockIdx.x * blockDim.x + threadIdx.x;   // 0..262143
    int k = i & 1023;
    float nema = ema_in[i] * 0.9f + 0.1f * g_dw[i];
    outEma[i] = nema;
    outEmb[i] = nema / g_smooth[k];
}

// ---------------------------------------------------------------------------
extern "C" void kernel_launch(void* const* d_in, const int* in_sizes, int n_in,
                              void* d_out, int out_size) {
    const float* x     = (const float*)d_in[0];
    const float* embed = (const float*)d_in[1];
    const float* cs    = (const float*)d_in[2];
    const float* ema   = (const float*)d_in[3];
    float* out = (float*)d_out;

    // resolve spill pointer (in case the layout assumption is wrong, extras
    // go to scratch so we never write out of bounds)
    float* spill = nullptr;
    cudaGetSymbolAddress((void**)&spill, g_spill);

    const bool full = (out_size >= FULL_OUT);
    float* pIdx  = full ? out + IDX_OFF  : spill;
    float* pLoss = full ? out + LOSS_OFF : spill;
    float* pEmb  = full ? out + EMB_OFF  : spill;
    float* pCS   = full ? out + CS_OFF   : spill;
    float* pEma  = full ? out + EMA_OFF  : spill;

    prep_kernel<<<1024, 256>>>(embed);
    argmin_kernel<<<NROWS / 64, 256>>>(x, embed, pIdx);
    writeback_kernel<<<32768, 256>>>(x, embed, out);
    cs_kernel<<<1, 1024>>>(cs, pCS, pLoss);
    emb_kernel<<<1024, 256>>>(ema, pEmb, pEma);
}

// round 3
// speedup vs baseline: 2.1277x; 2.1277x over previous
#include <cuda_runtime.h>
#include <cuda_fp16.h>
#include <cstdint>

// ---------------------------------------------------------------------------
// FeatureQuantizerEMA — VQ-VAE EMA quantizer, mma.sync fp16-split argmin
// outputs concatenated f32: out(33554432), loss(1), embed_idx(131072),
//   new_embed(262144), new_cluster_size(1024), new_ema_embed(262144)
// ---------------------------------------------------------------------------

#define NROWS   131072
#define KEMB    1024
#define DEMB    256
#define HWSZ    4096

#define LOSS_OFF 33554432
#define IDX_OFF  33554433
#define EMB_OFF  33685505
#define CS_OFF   33947649
#define EMA_OFF  33948673
#define FULL_OUT 34210817

// scratch
__device__ int     g_idx[NROWS];
__device__ float   g_count[KEMB];
__device__ float   g_dw[DEMB * KEMB];
__device__ float   g_e2h[KEMB];
__device__ float   g_smooth[KEMB];
__device__ double  g_lossPart[256];
__device__ float   g_spill[262144];
__device__ __half  g_Ehf[KEMB * DEMB];   // E^T hi, codes-major [k][d]
__device__ __half  g_Elf[KEMB * DEMB];   // E^T lo

__device__ __forceinline__ uint32_t smem_to_u32(const void* p) {
    uint32_t a;
    asm("{ .reg .u64 t; cvta.to.shared.u64 t, %1; cvt.u32.u64 %0, t; }"
        : "=r"(a) : "l"(p));
    return a;
}

#define LDSM4(r0, r1, r2, r3, a) \
    asm volatile("ldmatrix.sync.aligned.m8n8.x4.shared.b16 {%0,%1,%2,%3}, [%4];" \
                 : "=r"(r0), "=r"(r1), "=r"(r2), "=r"(r3) : "r"(a))
#define LDSM4T(r0, r1, r2, r3, a) \
    asm volatile("ldmatrix.sync.aligned.m8n8.x4.trans.shared.b16 {%0,%1,%2,%3}, [%4];" \
                 : "=r"(r0), "=r"(r1), "=r"(r2), "=r"(r3) : "r"(a))

#define MMA16816(c, a0, a1, a2, a3, b0, b1) \
    asm volatile("mma.sync.aligned.m16n8k16.row.col.f32.f16.f16.f32 " \
                 "{%0,%1,%2,%3}, {%4,%5,%6,%7}, {%8,%9}, {%0,%1,%2,%3};" \
                 : "+f"((c)[0]), "+f"((c)[1]), "+f"((c)[2]), "+f"((c)[3]) \
                 : "r"(a0), "r"(a1), "r"(a2), "r"(a3), "r"(b0), "r"(b1))

// ===========================================================================
// prep: zero dw/count/loss, embed half-norms (fp32), E^T fp16 hi/lo split
// ===========================================================================
__global__ void prep_kernel(const float* __restrict__ embed) {
    int i = blockIdx.x * blockDim.x + threadIdx.x;
    if (i < DEMB * KEMB) {
        g_dw[i] = 0.0f;
        int k = i & (KEMB - 1);
        int d = i >> 10;
        float v = embed[i];                       // embed[d][k]
        __half h = __float2half_rn(v);
        float r = v - __half2float(h);
        g_Ehf[k * DEMB + d] = h;
        g_Elf[k * DEMB + d] = __float2half_rn(r);
    }
    if (i < KEMB) {
        g_count[i] = 0.0f;
        float s = 0.0f;
        #pragma unroll 4
        for (int d = 0; d < DEMB; d++) {
            float e = embed[d * KEMB + i];
            s = fmaf(e, e, s);
        }
        g_e2h[i] = 0.5f * s;
    }
    if (i < 256) g_lossPart[i] = 0.0;
}

// ===========================================================================
// argmin: mma.sync fp16-split GEMM + fused argmin
//  CTA = 128 rows x 1024 codes, 256 threads (8 warps, 4m x 2n).
//  A (x hi/lo) k-major in smem, ldmatrix.trans. B streamed in 64-k chunks,
//  double buffered. Accumulate 3 products in fp32: Ah*Bh + Ah*Bl + Al*Bh.
// ===========================================================================
#define PA 136                       // A pitch (m) in halfs
#define PB 72                        // B pitch (k) in halfs
#define SM_E2H 0                     // 4096 B
#define SM_A   4096                  // A hi: 256*136*2 = 69632
#define SM_ALO (4096 + 69632)        // A lo
#define SM_B   (4096 + 2 * 69632)    // 143360: 2 stages x 2 mats x 18432
#define SM_RED SM_B                  // alias (after GEMM done)
#define SM_TOT (SM_B + 4 * 18432)    // 217088

__device__ __forceinline__ void loadB(char* smem, int chunk, int tid) {
    const int stage = chunk & 1;
    const int nb = chunk >> 2, kc = chunk & 3;
    #pragma unroll
    for (int j = 0; j < 8; j++) {
        int i = tid + j * 256;           // 0..2047
        int mat = i >> 10;               // 0=hi 1=lo
        int r   = (i >> 3) & 127;        // code row within block
        int c   = i & 7;                 // 16B chunk along k
        const __half* src = (mat ? g_Elf : g_Ehf)
                          + ((size_t)(nb * 128 + r) << 8) + kc * 64 + c * 8;
        uint4 v = *(const uint4*)src;
        *(uint4*)(smem + SM_B + stage * 36864 + mat * 18432 + r * (PB * 2) + c * 16) = v;
    }
}

__global__ __launch_bounds__(256, 1)
void argmin_mma_kernel(const float* __restrict__ x, float* __restrict__ outIdxF) {
    extern __shared__ char smem[];
    const uint32_t sb = smem_to_u32(smem);
    const int tid = threadIdx.x, lane = tid & 31, wid = tid >> 5;
    const int wm = wid & 3, wn = wid >> 2;

    float* e2h = (float*)(smem + SM_E2H);
    for (int i = tid; i < KEMB; i += 256) e2h[i] = g_e2h[i];

    // stage A (x rows) as fp16 hi/lo, k-major [d][m], pitch PA
    const int n0 = blockIdx.x << 7;
    const float* xb = x + ((size_t)(n0 >> 12) << 20) + (n0 & (HWSZ - 1));
    __half* Ah = (__half*)(smem + SM_A);
    __half* Al = (__half*)(smem + SM_ALO);
    for (int i = tid; i < 32768; i += 256) {
        int d = i >> 7, m = i & 127;
        float v = xb[(size_t)d * HWSZ + m];
        __half h = __float2half_rn(v);
        float r = v - __half2float(h);
        Ah[d * PA + m] = h;
        Al[d * PA + m] = __float2half_rn(r);
    }
    loadB(smem, 0, tid);
    __syncthreads();

    // lane geometry
    const int g = lane >> 2, t = lane & 3;
    const uint32_t a_k = (uint32_t)((lane & 7) + ((lane & 16) ? 8 : 0));
    const uint32_t a_m = (uint32_t)((lane & 8) ? 8 : 0);
    const uint32_t b_n = (uint32_t)((lane & 7) + ((lane & 16) ? 8 : 0));
    const uint32_t b_k = (uint32_t)((lane & 8) ? 8 : 0);

    float bs[4];
    int   bk[4];
    #pragma unroll
    for (int s = 0; s < 4; s++) { bs[s] = 3.4e38f; bk[s] = 0; }

    #pragma unroll 1
    for (int nb = 0; nb < 8; nb++) {
        float c[2][8][4];
        #pragma unroll
        for (int mt = 0; mt < 2; mt++)
            #pragma unroll
            for (int nt = 0; nt < 8; nt++)
                #pragma unroll
                for (int q = 0; q < 4; q++) c[mt][nt][q] = 0.0f;

        #pragma unroll 1
        for (int kc = 0; kc < 4; kc++) {
            const int chunk = nb * 4 + kc;
            if (chunk < 31) loadB(smem, chunk + 1, tid);
            const uint32_t bbase = sb + SM_B + (uint32_t)(chunk & 1) * 36864;

            #pragma unroll
            for (int ks = 0; ks < 4; ks++) {
                const uint32_t kA = (uint32_t)(kc * 64 + ks * 16);
                uint32_t ah[2][4], al[2][4];
                #pragma unroll
                for (int mt = 0; mt < 2; mt++) {
                    uint32_t aaddr = sb + SM_A
                        + ((kA + a_k) * PA + (uint32_t)(wm * 32 + mt * 16) + a_m) * 2;
                    LDSM4T(ah[mt][0], ah[mt][1], ah[mt][2], ah[mt][3], aaddr);
                    LDSM4T(al[mt][0], al[mt][1], al[mt][2], al[mt][3], aaddr + 69632);
                }
                uint32_t bh[4][4], bl[4][4];
                #pragma unroll
                for (int p = 0; p < 4; p++) {
                    uint32_t baddr = bbase
                        + (((uint32_t)(wn * 64 + p * 16) + b_n) * PB
                           + (uint32_t)(ks * 16) + b_k) * 2;
                    LDSM4(bh[p][0], bh[p][1], bh[p][2], bh[p][3], baddr);
                    LDSM4(bl[p][0], bl[p][1], bl[p][2], bl[p][3], baddr + 18432);
                }
                #pragma unroll
                for (int p = 0; p < 4; p++) {
                    #pragma unroll
                    for (int mt = 0; mt < 2; mt++) {
                        MMA16816(c[mt][2 * p],     ah[mt][0], ah[mt][1], ah[mt][2], ah[mt][3], bh[p][0], bh[p][1]);
                        MMA16816(c[mt][2 * p + 1], ah[mt][0], ah[mt][1], ah[mt][2], ah[mt][3], bh[p][2], bh[p][3]);
                        MMA16816(c[mt][2 * p],     ah[mt][0], ah[mt][1], ah[mt][2], ah[mt][3], bl[p][0], bl[p][1]);
                        MMA16816(c[mt][2 * p + 1], ah[mt][0], ah[mt][1], ah[mt][2], ah[mt][3], bl[p][2], bl[p][3]);
                        MMA16816(c[mt][2 * p],     al[mt][0], al[mt][1], al[mt][2], al[mt][3], bh[p][0], bh[p][1]);
                        MMA16816(c[mt][2 * p + 1], al[mt][0], al[mt][1], al[mt][2], al[mt][3], bh[p][2], bh[p][3]);
                    }
                }
            }
            __syncthreads();
        }

        // fused argmin epilogue for this 128-code block (ascending k order)
        #pragma unroll
        for (int mt = 0; mt < 2; mt++) {
            #pragma unroll
            for (int nt = 0; nt < 8; nt++) {
                int n = nb * 128 + wn * 64 + nt * 8 + 2 * t;
                float s0 = e2h[n]     - c[mt][nt][0];
                float s1 = e2h[n + 1] - c[mt][nt][1];
                float s2 = e2h[n]     - c[mt][nt][2];
                float s3 = e2h[n + 1] - c[mt][nt][3];
                int s = mt * 2;
                if (s0 < bs[s])     { bs[s] = s0;     bk[s] = n; }
                if (s1 < bs[s])     { bs[s] = s1;     bk[s] = n + 1; }
                if (s2 < bs[s + 1]) { bs[s + 1] = s2; bk[s + 1] = n; }
                if (s3 < bs[s + 1]) { bs[s + 1] = s3; bk[s + 1] = n + 1; }
            }
        }
    }

    // reduce over the 4 t-lanes holding the same rows
    #pragma unroll
    for (int s = 0; s < 4; s++) {
        #pragma unroll
        for (int off = 1; off <= 2; off <<= 1) {
            float so = __shfl_xor_sync(0xffffffffu, bs[s], off);
            int   ko = __shfl_xor_sync(0xffffffffu, bk[s], off);
            if (so < bs[s] || (so == bs[s] && ko < bk[s])) { bs[s] = so; bk[s] = ko; }
        }
    }
    __syncthreads();
    float* rS = (float*)(smem + SM_RED);          // [2][128]
    int*   rK = (int*)(smem + SM_RED + 1024);
    if (t == 0) {
        #pragma unroll
        for (int s = 0; s < 4; s++) {
            int row = wm * 32 + (s >> 1) * 16 + (s & 1) * 8 + g;
            rS[wn * 128 + row] = bs[s];
            rK[wn * 128 + row] = bk[s];
        }
    }
    __syncthreads();
    if (tid < 128) {
        float s0 = rS[tid], s1 = rS[128 + tid];
        int   k0 = rK[tid], k1 = rK[128 + tid];
        int kb = (s1 < s0 || (s1 == s0 && k1 < k0)) ? k1 : k0;
        int n = n0 + tid;
        g_idx[n] = kb;
        outIdxF[n] = (float)kb;
        atomicAdd(&g_count[kb], 1.0f);
    }
}

// ===========================================================================
// writeback: out = gather(embed, idx), loss partials, dw scatter
// ===========================================================================
__global__ __launch_bounds__(256)
void writeback_kernel(const float* __restrict__ x,
                      const float* __restrict__ embed,
                      float* __restrict__ out) {
    const int t = blockIdx.x * blockDim.x + threadIdx.x;
    const size_t e = (size_t)t * 4;
    const int b   = (int)(e >> 20);
    const int rem = (int)(e & 1048575);
    const int d   = rem >> 12;
    const int hw  = rem & 4095;
    const int n   = (b << 12) | hw;

    float4 xv = *(const float4*)(x + e);
    int4   kv = *(const int4*)(g_idx + n);
    const float* erow = embed + (size_t)d * KEMB;
    float q0 = __ldg(erow + kv.x);
    float q1 = __ldg(erow + kv.y);
    float q2 = __ldg(erow + kv.z);
    float q3 = __ldg(erow + kv.w);
    *(float4*)(out + e) = make_float4(q0, q1, q2, q3);

    float d0 = q0 - xv.x, d1 = q1 - xv.y, d2 = q2 - xv.z, d3 = q3 - xv.w;
    float ls = d0 * d0 + d1 * d1 + d2 * d2 + d3 * d3;

    float* dwrow = g_dw + (size_t)d * KEMB;
    atomicAdd(dwrow + kv.x, xv.x);
    atomicAdd(dwrow + kv.y, xv.y);
    atomicAdd(dwrow + kv.z, xv.z);
    atomicAdd(dwrow + kv.w, xv.w);

    #pragma unroll
    for (int off = 16; off; off >>= 1)
        ls += __shfl_xor_sync(0xffffffffu, ls, off);
    __shared__ float wsum[8];
    int lane = threadIdx.x & 31, w = threadIdx.x >> 5;
    if (lane == 0) wsum[w] = ls;
    __syncthreads();
    if (threadIdx.x == 0) {
        float bsum = 0.0f;
        #pragma unroll
        for (int i = 0; i < 8; i++) bsum += wsum[i];
        atomicAdd(&g_lossPart[blockIdx.x & 255], (double)bsum);
    }
}

// ===========================================================================
__global__ __launch_bounds__(1024)
void cs_kernel(const float* __restrict__ cs_in,
               float* __restrict__ outCS,
               float* __restrict__ outLoss) {
    __shared__ float red[1024];
    int k = threadIdx.x;
    float ncs = cs_in[k] * 0.9f + 0.1f * g_count[k];
    outCS[k] = ncs;
    red[k] = ncs;
    __syncthreads();
    for (int s = 512; s; s >>= 1) {
        if (k < s) red[k] += red[k + s];
        __syncthreads();
    }
    float nsum = red[0];
    g_smooth[k] = nsum * ((ncs + 1e-5f) / (nsum + ncs * 1e-5f));
    if (k == 0) {
        double ls = 0.0;
        for (int i = 0; i < 256; i++) ls += g_lossPart[i];
        outLoss[0] = (float)(0.25 * ls / 33554432.0);
    }
}

__global__ __launch_bounds__(256)
void emb_kernel(const float* __restrict__ ema_in,
                float* __restrict__ outEmb,
                float* __restrict__ outEma) {
    int i = blockIdx.x * blockDim.x + threadIdx.x;
    int k = i & 1023;
    float nema = ema_in[i] * 0.9f + 0.1f * g_dw[i];
    outEma[i] = nema;
    outEmb[i] = nema / g_smooth[k];
}

// ===========================================================================
extern "C" void kernel_launch(void* const* d_in, const int* in_sizes, int n_in,
                              void* d_out, int out_size) {
    const float* x     = (const float*)d_in[0];
    const float* embed = (const float*)d_in[1];
    const float* cs    = (const float*)d_in[2];
    const float* ema   = (const float*)d_in[3];
    float* out = (float*)d_out;

    float* spill = nullptr;
    cudaGetSymbolAddress((void**)&spill, g_spill);

    const bool full = (out_size >= FULL_OUT);
    float* pIdx  = full ? out + IDX_OFF  : spill;
    float* pLoss = full ? out + LOSS_OFF : spill;
    float* pEmb  = full ? out + EMB_OFF  : spill;
    float* pCS   = full ? out + CS_OFF   : spill;
    float* pEma  = full ? out + EMA_OFF  : spill;

    cudaFuncSetAttribute(argmin_mma_kernel,
                         cudaFuncAttributeMaxDynamicSharedMemorySize, SM_TOT);

    prep_kernel<<<1024, 256>>>(embed);
    argmin_mma_kernel<<<NROWS / 128, 256, SM_TOT>>>(x, pIdx);
    writeback_kernel<<<32768, 256>>>(x, embed, out);
    cs_kernel<<<1, 1024>>>(cs, pCS, pLoss);
    emb_kernel<<<1024, 256>>>(ema, pEmb, pEma);
}